// round 11
// baseline (speedup 1.0000x reference)
#include <cuda_runtime.h>
#include <cuda_fp16.h>
#include <stdint.h>

// Problem constants: T=4, B=4, N=512, D=512, F=2048, H=8, dh=64
#define ROWS   8192              // T*B*N
#define DMODEL 512
#define FDIM   2048
#define S512   (ROWS*DMODEL/4)   // B*N*D  (per-timestep spatial size)

// ---------------- scratch (allocation-free: __device__ globals) ----------------
__device__ float g_x   [ROWS*DMODEL];      // running residual stream (fp32)
__device__ float g_pre [ROWS*DMODEL];      // pre-activation scratch (width 512)
__device__ float g_pre2[ROWS*FDIM];        // pre-activation scratch (width up to 2048)
__device__ __half g_as[2*ROWS*DMODEL];     // activation limbs (x)
__device__ __half g_es[2*ROWS*DMODEL];     // activation limbs (enc)
__device__ __half g_qb[ROWS*DMODEL];       // cross-attn q spikes
__device__ __half g_tb[ROWS*DMODEL];       // attn-out spikes
__device__ __half g_hb[ROWS*FDIM];         // qkv spikes / kv spikes / MLP hidden spikes
// weight limbs, transposed [N][K], limb1 at offset N*K
__device__ __half g_w_qkv[2*1536*DMODEL];
__device__ __half g_w_os [2*DMODEL*DMODEL];
__device__ __half g_w_qc [2*DMODEL*DMODEL];
__device__ __half g_w_kvc[2*1024*DMODEL];
__device__ __half g_w_oc [2*DMODEL*DMODEL];
__device__ __half g_w_1  [2*FDIM*DMODEL];
__device__ __half g_w_2  [2*DMODEL*FDIM];
__device__ float  g_bqkv[1536];
__device__ float  g_bkvc[1024];

// ---------------- small helpers ----------------
__device__ __forceinline__ uint32_t smem_u32(const void* p) {
    return (uint32_t)__cvta_generic_to_shared(p);
}

// ---------------- split / fused elementwise kernels ----------------
__global__ void copy_split(const float* __restrict__ X, float* __restrict__ gx,
                           __half* __restrict__ a0, __half* __restrict__ a1, int n)
{
    int i = blockIdx.x * blockDim.x + threadIdx.x;
    if (i >= n) return;
    float v = X[i];
    gx[i] = v;
    __half h = __float2half(v);
    a0[i] = h;
    a1[i] = __float2half(v - __half2float(h));
}

__global__ void asplit2(const float* __restrict__ X,
                        __half* __restrict__ a0, __half* __restrict__ a1, int n)
{
    int i = blockIdx.x * blockDim.x + threadIdx.x;
    if (i >= n) return;
    float v = X[i];
    __half h = __float2half(v);
    a0[i] = h;
    a1[i] = __float2half(v - __half2float(h));
}

// W[K][N] fp32 -> 2 fp16 limbs transposed [N][K] (dst row stride = K)
__global__ void wsplit2(const float* __restrict__ W,
                        __half* __restrict__ w0, __half* __restrict__ w1, int K, int N)
{
    __shared__ float t[32][33];
    const int tid = threadIdx.x;
    const int n0 = blockIdx.x * 32;
    const int k0 = blockIdx.y * 32;
    for (int i = tid; i < 1024; i += 256) {
        int r = i >> 5, c = i & 31;
        t[r][c] = W[(size_t)(k0 + r) * N + n0 + c];
    }
    __syncthreads();
    for (int i = tid; i < 1024; i += 256) {
        int r = i >> 5, c = i & 31;
        float x = t[c][r];
        __half h = __float2half(x);
        __half m = __float2half(x - __half2float(h));
        size_t o = (size_t)(n0 + r) * K + k0 + c;
        w0[o] = h; w1[o] = m;
    }
}

__global__ void copyvec(float* __restrict__ dst, const float* __restrict__ src, int n)
{
    int i = blockIdx.x * blockDim.x + threadIdx.x;
    if (i < n) dst[i] = src[i];
}

// LIF over T=4 (elementwise in columns): pre fp32 [4,S] -> spikes fp16 [4,S]
__global__ void lif4h(const float* __restrict__ pre, __half* __restrict__ out, int S)
{
    const int i = blockIdx.x * blockDim.x + threadIdx.x;
    if (i >= S) return;
    float vmem = 0.f;
    #pragma unroll
    for (int t = 0; t < 4; t++) {
        float u = (vmem + pre[(size_t)t * S + i]) * 0.5f;
        if (u >= 1.0f) { out[(size_t)t * S + i] = __float2half(1.0f); vmem = 0.0f; }
        else           { out[(size_t)t * S + i] = __float2half(0.0f); vmem = u;    }
    }
}

// LIF + residual add into x, and write fp16 limbs of the new x
__global__ void lif4_add_split(const float* __restrict__ pre, float* __restrict__ x,
                               __half* __restrict__ a0, __half* __restrict__ a1, int S)
{
    const int i = blockIdx.x * blockDim.x + threadIdx.x;
    if (i >= S) return;
    float vmem = 0.f;
    #pragma unroll
    for (int t = 0; t < 4; t++) {
        const size_t idx = (size_t)t * S + i;
        float u = (vmem + pre[idx]) * 0.5f;
        float xn = x[idx];
        if (u >= 1.0f) { xn += 1.0f; vmem = 0.0f; }
        else           { vmem = u; }
        x[idx] = xn;
        __half h = __float2half(xn);
        a0[idx] = h;
        a1[idx] = __float2half(xn - __half2float(h));
    }
}

// LIF + residual add, final result straight to out
__global__ void lif4_add_out(const float* __restrict__ pre, const float* __restrict__ x,
                             float* __restrict__ out, int S)
{
    const int i = blockIdx.x * blockDim.x + threadIdx.x;
    if (i >= S) return;
    float vmem = 0.f;
    #pragma unroll
    for (int t = 0; t < 4; t++) {
        const size_t idx = (size_t)t * S + i;
        float u = (vmem + pre[idx]) * 0.5f;
        float s;
        if (u >= 1.0f) { s = 1.0f; vmem = 0.0f; }
        else           { s = 0.0f; vmem = u; }
        out[idx] = x[idx] + s;
    }
}

// ---------------- GEMM: C[M,Ntot] = sum_seg A_seg[M,K] @ Wt_seg[Ntot,K]^T + bias ----------
// CTA tile 128x128, 256 threads, mma.sync m16n8k16 fp16->fp32,
// 4-stage cp.async pipeline with ONE __syncthreads per k-iteration.
struct Segs { const __half* a[3]; const __half* w[3]; };

#define STAGE_B 20480            // per stage: A 128x40h (10240B) + W 128x40h
#define DSM (4*STAGE_B + 256)

__global__ __launch_bounds__(256) void gemm_u(
    Segs segs, int nseg, const float* __restrict__ bias,
    float* __restrict__ C, int N, int K)
{
    extern __shared__ char dyn[];
    const uint32_t base = (smem_u32(dyn) + 15) & ~15u;

    const int tid  = threadIdx.x;
    const int lane = tid & 31;
    const int warp = tid >> 5;
    const int m0   = blockIdx.y * 128;
    const int n0   = blockIdx.x * 128;

    const int wm = warp >> 2;   // 0..1 -> 64 rows
    const int wn = warp & 3;    // 0..3 -> 32 cols
    const int r  = lane >> 2;
    const int q  = lane & 3;

    const int aRow = (lane & 7) + ((lane >> 3) & 1) * 8;
    const int aCol = (lane >> 4) * 8;
    const int bRow = (lane & 7) + (lane >> 4) * 8;
    const int bCol = ((lane >> 3) & 1) * 8;

    float acc[4][4][4];
    #pragma unroll
    for (int i = 0; i < 4; i++)
        #pragma unroll
        for (int j = 0; j < 4; j++)
            #pragma unroll
            for (int z = 0; z < 4; z++) acc[i][j][z] = 0.f;

    const int ktiles = K >> 5;
    const int TT = nseg * ktiles;

    auto issue = [&](int t) {
        const int buf = t & 3;
        const __half* ap = segs.a[t / ktiles];
        const __half* wp = segs.w[t / ktiles];
        const int kk = (t % ktiles) << 5;
        #pragma unroll
        for (int u = 0; u < 2; ++u) {
            const int c   = tid + (u << 8);
            const int row = c >> 2;
            const int col = (c & 3) << 3;  // halves (8 per 16B)
            const __half* sa = ap + (size_t)(m0 + row) * K + kk + col;
            const __half* sw = wp + (size_t)(n0 + row) * K + kk + col;
            const uint32_t da = base + buf * STAGE_B + (uint32_t)(row * 40 + col) * 2;
            const uint32_t dw = da + 10240;
            asm volatile("cp.async.cg.shared.global [%0], [%1], 16;" :: "r"(da), "l"(sa));
            asm volatile("cp.async.cg.shared.global [%0], [%1], 16;" :: "r"(dw), "l"(sw));
        }
        asm volatile("cp.async.commit_group;");
    };

    issue(0);
    issue(1);

    for (int tt = 0; tt < TT; ++tt) {
        if (tt + 2 < TT) {
            issue(tt + 2);
            asm volatile("cp.async.wait_group 2;");
        } else if (tt + 1 < TT) {
            asm volatile("cp.async.wait_group 1;");
        } else {
            asm volatile("cp.async.wait_group 0;");
        }
        __syncthreads();

        const int buf = tt & 3;
        const uint32_t aT = base + buf * STAGE_B;
        const uint32_t wT = aT + 10240;

        #pragma unroll
        for (int ko = 0; ko < 32; ko += 16) {
            uint32_t af[4][4], bfr[4][2];
            #pragma unroll
            for (int i = 0; i < 4; i++) {
                const uint32_t addr = aT +
                    (uint32_t)((wm * 64 + i * 16 + aRow) * 40 + ko + aCol) * 2;
                asm volatile(
                    "ldmatrix.sync.aligned.m8n8.x4.shared.b16 {%0,%1,%2,%3}, [%4];"
                    : "=r"(af[i][0]), "=r"(af[i][1]), "=r"(af[i][2]), "=r"(af[i][3])
                    : "r"(addr));
            }
            #pragma unroll
            for (int jj = 0; jj < 2; jj++) {
                const uint32_t addr = wT +
                    (uint32_t)((wn * 32 + jj * 16 + bRow) * 40 + ko + bCol) * 2;
                asm volatile(
                    "ldmatrix.sync.aligned.m8n8.x4.shared.b16 {%0,%1,%2,%3}, [%4];"
                    : "=r"(bfr[2*jj][0]), "=r"(bfr[2*jj][1]),
                      "=r"(bfr[2*jj+1][0]), "=r"(bfr[2*jj+1][1])
                    : "r"(addr));
            }
            #pragma unroll
            for (int i = 0; i < 4; i++)
                #pragma unroll
                for (int j = 0; j < 4; j++)
                    asm volatile(
                        "mma.sync.aligned.m16n8k16.row.col.f32.f16.f16.f32 "
                        "{%0,%1,%2,%3}, {%4,%5,%6,%7}, {%8,%9}, {%0,%1,%2,%3};"
                        : "+f"(acc[i][j][0]), "+f"(acc[i][j][1]),
                          "+f"(acc[i][j][2]), "+f"(acc[i][j][3])
                        : "r"(af[i][0]), "r"(af[i][1]), "r"(af[i][2]), "r"(af[i][3]),
                          "r"(bfr[j][0]), "r"(bfr[j][1]));
        }
    }

    // epilogue: bias add + fp32 store
    #pragma unroll
    for (int i = 0; i < 4; i++) {
        const int R0 = m0 + wm * 64 + i * 16 + r;
        #pragma unroll
        for (int j = 0; j < 4; j++) {
            const int C0 = n0 + wn * 32 + j * 8 + 2 * q;
            const float b0 = bias[C0], b1 = bias[C0 + 1];
            float2 o0, o1;
            o0.x = acc[i][j][0] + b0; o0.y = acc[i][j][1] + b1;
            o1.x = acc[i][j][2] + b0; o1.y = acc[i][j][3] + b1;
            *(float2*)&C[(size_t)R0 * N + C0] = o0;
            *(float2*)&C[(size_t)(R0 + 8) * N + C0] = o1;
        }
    }
}

// ---------------- Attention: out = q (kT v) * alpha, binary fp16 spikes, strided ----------
__device__ __forceinline__ void unp8h(const __half* g, float* dst)
{
    uint4 u = *reinterpret_cast<const uint4*>(g);
    const __half2* p = reinterpret_cast<const __half2*>(&u);
    #pragma unroll
    for (int z = 0; z < 4; z++) {
        float2 f = __half22float2(p[z]);
        dst[2 * z] = f.x; dst[2 * z + 1] = f.y;
    }
}

__global__ __launch_bounds__(256) void attn_kernel(
    const __half* __restrict__ q, int qstride,
    const __half* __restrict__ k, const __half* __restrict__ v, int kvstride,
    float* __restrict__ out)
{
    __shared__ float ktv[64][64];
    __shared__ float ks [64][64];
    __shared__ float vs [64][64];

    const int tid     = threadIdx.x;
    const int h       = blockIdx.x & 7;
    const int tb      = blockIdx.x >> 3;
    const int rowbase = tb * 512;
    const int cbase   = h * 64;

    const int d  = tid >> 2;
    const int e0 = (tid & 3) * 16;
    float acc[16];
    #pragma unroll
    for (int j = 0; j < 16; j++) acc[j] = 0.f;

    for (int m0 = 0; m0 < 512; m0 += 64) {
        for (int i = tid; i < 512; i += 256) {
            const int r = i >> 3;
            const int c = (i & 7) * 8;
            const size_t go = (size_t)(rowbase + m0 + r) * kvstride + cbase + c;
            unp8h(k + go, &ks[r][c]);
            unp8h(v + go, &vs[r][c]);
        }
        __syncthreads();
        #pragma unroll 4
        for (int mm = 0; mm < 64; mm++) {
            const float kd = ks[mm][d];
            if (kd != 0.f) {
                #pragma unroll
                for (int j = 0; j < 16; j++) acc[j] += vs[mm][e0 + j];
            }
        }
        __syncthreads();
    }
    #pragma unroll
    for (int j = 0; j < 16; j++) ktv[d][e0 + j] = acc[j];
    __syncthreads();

    for (int n0 = 0; n0 < 512; n0 += 64) {
        for (int i = tid; i < 512; i += 256) {
            const int r = i >> 3;
            const int c = (i & 7) * 8;
            unp8h(q + (size_t)(rowbase + n0 + r) * qstride + cbase + c, &ks[r][c]);
        }
        __syncthreads();
        const int rn  = tid >> 2;
        const int ee0 = (tid & 3) * 16;
        float o[16];
        #pragma unroll
        for (int j = 0; j < 16; j++) o[j] = 0.f;
        #pragma unroll 4
        for (int dd = 0; dd < 64; dd++) {
            const float qd = ks[rn][dd];
            if (qd != 0.f) {
                #pragma unroll
                for (int j = 0; j < 16; j++) o[j] += ktv[dd][ee0 + j];
            }
        }
        #pragma unroll
        for (int j = 0; j < 16; j += 4) {
            float4 ov;
            ov.x = o[j + 0] * 0.125f; ov.y = o[j + 1] * 0.125f;
            ov.z = o[j + 2] * 0.125f; ov.w = o[j + 3] * 0.125f;
            *(float4*)&out[(size_t)(rowbase + n0 + rn) * 512 + cbase + ee0 + j] = ov;
        }
        __syncthreads();
    }
}

// ---------------- host-side orchestration ----------------
static void launch_gemm(const __half* a0, const __half* a1, const __half* w,
                        int nseg, const float* bias, float* C, int N, int K)
{
    // nseg==3: fp32-A (h,h)(m,h)(h,m); nseg==2: binary-A (s,h)(s,m)
    Segs s;
    const size_t SW = (size_t)N * K;
    if (nseg == 3) {
        s.a[0] = a0; s.w[0] = w;
        s.a[1] = a1; s.w[1] = w;
        s.a[2] = a0; s.w[2] = w + SW;
    } else {
        s.a[0] = a0; s.w[0] = w;
        s.a[1] = a0; s.w[1] = w + SW;
        s.a[2] = a0; s.w[2] = w;
    }
    cudaFuncSetAttribute(gemm_u, cudaFuncAttributeMaxDynamicSharedMemorySize, DSM);
    gemm_u<<<dim3(N / 128, ROWS / 128), 256, DSM>>>(s, nseg, bias, C, N, K);
}

extern "C" void kernel_launch(void* const* d_in, const int* in_sizes, int n_in,
                              void* d_out, int out_size)
{
    const float* x    = (const float*)d_in[0];
    const float* enc  = (const float*)d_in[1];
    const float* Wq_s = (const float*)d_in[2];  const float* bq_s = (const float*)d_in[3];
    const float* Wk_s = (const float*)d_in[4];  const float* bk_s = (const float*)d_in[5];
    const float* Wv_s = (const float*)d_in[6];  const float* bv_s = (const float*)d_in[7];
    const float* Wo_s = (const float*)d_in[8];  const float* bo_s = (const float*)d_in[9];
    const float* Wq_c = (const float*)d_in[10]; const float* bq_c = (const float*)d_in[11];
    const float* Wk_c = (const float*)d_in[12]; const float* bk_c = (const float*)d_in[13];
    const float* Wv_c = (const float*)d_in[14]; const float* bv_c = (const float*)d_in[15];
    const float* Wo_c = (const float*)d_in[16]; const float* bo_c = (const float*)d_in[17];
    const float* W1   = (const float*)d_in[18]; const float* b1   = (const float*)d_in[19];
    const float* W2   = (const float*)d_in[20]; const float* b2   = (const float*)d_in[21];

    float *gx, *gpre, *gpre2, *bqkv, *bkvc;
    __half *asb, *esb, *qb, *tb, *hb;
    __half *w_qkv, *w_os, *w_qc, *w_kvc, *w_oc, *w_1, *w_2;
    cudaGetSymbolAddress((void**)&gx,    g_x);
    cudaGetSymbolAddress((void**)&gpre,  g_pre);
    cudaGetSymbolAddress((void**)&gpre2, g_pre2);
    cudaGetSymbolAddress((void**)&asb,   g_as);
    cudaGetSymbolAddress((void**)&esb,   g_es);
    cudaGetSymbolAddress((void**)&qb,    g_qb);
    cudaGetSymbolAddress((void**)&tb,    g_tb);
    cudaGetSymbolAddress((void**)&hb,    g_hb);
    cudaGetSymbolAddress((void**)&w_qkv, g_w_qkv);
    cudaGetSymbolAddress((void**)&w_os,  g_w_os);
    cudaGetSymbolAddress((void**)&w_qc,  g_w_qc);
    cudaGetSymbolAddress((void**)&w_kvc, g_w_kvc);
    cudaGetSymbolAddress((void**)&w_oc,  g_w_oc);
    cudaGetSymbolAddress((void**)&w_1,   g_w_1);
    cudaGetSymbolAddress((void**)&w_2,   g_w_2);
    cudaGetSymbolAddress((void**)&bqkv,  g_bqkv);
    cudaGetSymbolAddress((void**)&bkvc,  g_bkvc);

    const size_t SD = (size_t)ROWS * DMODEL;
    __half* as0 = asb; __half* as1 = asb + SD;
    __half* es0 = esb; __half* es1 = esb + SD;

    // lazily-created side stream + events (resources only; work is identical every call)
    static cudaStream_t s2 = nullptr;
    static cudaEvent_t evRoot, ev[6];
    if (!s2) {
        cudaStreamCreateWithFlags(&s2, cudaStreamNonBlocking);
        cudaEventCreateWithFlags(&evRoot, cudaEventDisableTiming);
        for (int i = 0; i < 6; i++) cudaEventCreateWithFlags(&ev[i], cudaEventDisableTiming);
    }

    const int nel = ROWS * DMODEL;
    const int lgD = S512 / 256;
    const dim3 wg512(16, 16);   // wsplit2 grid for 512x512

    // ---- fork side stream: weight/bias/enc preprocessing ----
    cudaEventRecord(evRoot, 0);
    cudaStreamWaitEvent(s2, evRoot, 0);

    // self qkv (merged [1536][512], limb1 at +1536*512)
    wsplit2<<<wg512, 256, 0, s2>>>(Wq_s, w_qkv,             w_qkv + 1536*512,             DMODEL, DMODEL);
    wsplit2<<<wg512, 256, 0, s2>>>(Wk_s, w_qkv + 512*512,   w_qkv + 1536*512 + 512*512,   DMODEL, DMODEL);
    wsplit2<<<wg512, 256, 0, s2>>>(Wv_s, w_qkv + 1024*512,  w_qkv + 1536*512 + 1024*512,  DMODEL, DMODEL);
    copyvec<<<2, 256, 0, s2>>>(bqkv,        bq_s, 512);
    copyvec<<<2, 256, 0, s2>>>(bqkv +  512, bk_s, 512);
    copyvec<<<2, 256, 0, s2>>>(bqkv + 1024, bv_s, 512);
    cudaEventRecord(ev[0], s2);

    wsplit2<<<wg512, 256, 0, s2>>>(Wo_s, w_os, w_os + 512*512, DMODEL, DMODEL);
    cudaEventRecord(ev[1], s2);

    asplit2<<<nel / 256, 256, 0, s2>>>(enc, es0, es1, nel);
    wsplit2<<<wg512, 256, 0, s2>>>(Wq_c, w_qc, w_qc + 512*512, DMODEL, DMODEL);
    wsplit2<<<wg512, 256, 0, s2>>>(Wk_c, w_kvc,            w_kvc + 1024*512,            DMODEL, DMODEL);
    wsplit2<<<wg512, 256, 0, s2>>>(Wv_c, w_kvc + 512*512,  w_kvc + 1024*512 + 512*512,  DMODEL, DMODEL);
    copyvec<<<2, 256, 0, s2>>>(bkvc,       bk_c, 512);
    copyvec<<<2, 256, 0, s2>>>(bkvc + 512, bv_c, 512);
    cudaEventRecord(ev[2], s2);

    wsplit2<<<wg512, 256, 0, s2>>>(Wo_c, w_oc, w_oc + 512*512, DMODEL, DMODEL);
    cudaEventRecord(ev[3], s2);

    wsplit2<<<dim3(64, 16), 256, 0, s2>>>(W1, w_1, w_1 + (size_t)FDIM*512, DMODEL, FDIM);
    cudaEventRecord(ev[4], s2);
    wsplit2<<<dim3(16, 64), 256, 0, s2>>>(W2, w_2, w_2 + (size_t)512*FDIM, FDIM, DMODEL);
    cudaEventRecord(ev[5], s2);

    // ---- main stream ----
    copy_split<<<nel / 256, 256>>>(x, gx, as0, as1, nel);

    // self-attention block: x = x + ssa(x, x)
    cudaStreamWaitEvent(0, ev[0], 0);
    launch_gemm(as0, as1, w_qkv, 3, bqkv, gpre2, 1536, DMODEL);
    lif4h<<<(ROWS/4)*1536 / 256, 256>>>(gpre2, hb, (ROWS/4)*1536);
    attn_kernel<<<128, 256>>>(hb, 1536, hb + 512, hb + 1024, 1536, gpre);
    lif4h<<<lgD, 256>>>(gpre, tb, S512);
    cudaStreamWaitEvent(0, ev[1], 0);
    launch_gemm(tb, tb, w_os, 2, bo_s, gpre, DMODEL, DMODEL);
    lif4_add_split<<<lgD, 256>>>(gpre, gx, as0, as1, S512);

    // cross-attention block: x = x + ssa(x, enc)
    cudaStreamWaitEvent(0, ev[2], 0);
    launch_gemm(as0, as1, w_qc, 3, bq_c, gpre, DMODEL, DMODEL);
    launch_gemm(es0, es1, w_kvc, 3, bkvc, gpre2, 1024, DMODEL);
    lif4h<<<lgD, 256>>>(gpre, qb, S512);
    lif4h<<<(ROWS/4)*1024 / 256, 256>>>(gpre2, hb, (ROWS/4)*1024);
    attn_kernel<<<128, 256>>>(qb, 512, hb, hb + 512, 1024, gpre);
    lif4h<<<lgD, 256>>>(gpre, tb, S512);
    cudaStreamWaitEvent(0, ev[3], 0);
    launch_gemm(tb, tb, w_oc, 2, bo_c, gpre, DMODEL, DMODEL);
    lif4_add_split<<<lgD, 256>>>(gpre, gx, as0, as1, S512);

    // MLP block: x = x + lif(lif(x@W1+b1)@W2+b2)
    cudaStreamWaitEvent(0, ev[4], 0);
    launch_gemm(as0, as1, w_1, 3, b1, gpre2, FDIM, DMODEL);
    lif4h<<<(ROWS/4)*FDIM / 256, 256>>>(gpre2, hb, (ROWS/4)*FDIM);
    cudaStreamWaitEvent(0, ev[5], 0);
    launch_gemm(hb, hb, w_2, 2, b2, gpre, DMODEL, FDIM);
    lif4_add_out<<<lgD, 256>>>(gpre, gx, (float*)d_out, S512);
}

// round 12
// speedup vs baseline: 1.0894x; 1.0894x over previous
#include <cuda_runtime.h>
#include <cuda_fp16.h>
#include <stdint.h>

// Problem constants: T=4, B=4, N=512, D=512, F=2048, H=8, dh=64
#define ROWS   8192              // T*B*N
#define DMODEL 512
#define FDIM   2048
#define S512   (ROWS*DMODEL/4)   // B*N*D  (per-timestep spatial size)

// ---------------- scratch (allocation-free: __device__ globals) ----------------
__device__ float g_x   [ROWS*DMODEL];      // running residual stream (fp32)
__device__ float g_pre [ROWS*DMODEL];      // pre-activation scratch (width 512)
__device__ float g_pre2[ROWS*FDIM];        // pre-activation scratch (width up to 2048)
__device__ __half g_as[2*ROWS*DMODEL];     // activation limbs (x)
__device__ __half g_es[2*ROWS*DMODEL];     // activation limbs (enc)
__device__ __half g_qb[ROWS*DMODEL];       // cross-attn q spikes
__device__ __half g_tb[ROWS*DMODEL];       // attn-out spikes
__device__ __half g_hb[ROWS*FDIM];         // qkv spikes / kv spikes / MLP hidden spikes
// weight limbs, transposed [N][K], limb1 at offset N*K
__device__ __half g_w_qkv[2*1536*DMODEL];
__device__ __half g_w_os [2*DMODEL*DMODEL];
__device__ __half g_w_qc [2*DMODEL*DMODEL];
__device__ __half g_w_kvc[2*1024*DMODEL];
__device__ __half g_w_oc [2*DMODEL*DMODEL];
__device__ __half g_w_1  [2*FDIM*DMODEL];
__device__ __half g_w_2  [2*DMODEL*FDIM];
__device__ float  g_bqkv[1536];
__device__ float  g_bkvc[1024];

// ---------------- small helpers ----------------
__device__ __forceinline__ uint32_t smem_u32(const void* p) {
    return (uint32_t)__cvta_generic_to_shared(p);
}

// ---------------- split / fused elementwise kernels ----------------
__global__ void copy_split(const float* __restrict__ X, float* __restrict__ gx,
                           __half* __restrict__ a0, __half* __restrict__ a1, int n)
{
    int i = blockIdx.x * blockDim.x + threadIdx.x;
    if (i >= n) return;
    float v = X[i];
    gx[i] = v;
    __half h = __float2half(v);
    a0[i] = h;
    a1[i] = __float2half(v - __half2float(h));
}

__global__ void asplit2(const float* __restrict__ X,
                        __half* __restrict__ a0, __half* __restrict__ a1, int n)
{
    int i = blockIdx.x * blockDim.x + threadIdx.x;
    if (i >= n) return;
    float v = X[i];
    __half h = __float2half(v);
    a0[i] = h;
    a1[i] = __float2half(v - __half2float(h));
}

// W[K][N] fp32 -> 2 fp16 limbs transposed [N][K] (dst row stride = K)
__global__ void wsplit2(const float* __restrict__ W,
                        __half* __restrict__ w0, __half* __restrict__ w1, int K, int N)
{
    __shared__ float t[32][33];
    const int tid = threadIdx.x;
    const int n0 = blockIdx.x * 32;
    const int k0 = blockIdx.y * 32;
    for (int i = tid; i < 1024; i += 256) {
        int r = i >> 5, c = i & 31;
        t[r][c] = W[(size_t)(k0 + r) * N + n0 + c];
    }
    __syncthreads();
    for (int i = tid; i < 1024; i += 256) {
        int r = i >> 5, c = i & 31;
        float x = t[c][r];
        __half h = __float2half(x);
        __half m = __float2half(x - __half2float(h));
        size_t o = (size_t)(n0 + r) * K + k0 + c;
        w0[o] = h; w1[o] = m;
    }
}

// concat biases: bqkv = [bq_s|bk_s|bv_s], bkvc = [bk_c|bv_c]
__global__ void bias_concat(const float* __restrict__ bq, const float* __restrict__ bk,
                            const float* __restrict__ bv, const float* __restrict__ bkc,
                            const float* __restrict__ bvc,
                            float* __restrict__ bqkv, float* __restrict__ bkvc)
{
    int i = blockIdx.x * blockDim.x + threadIdx.x;   // 0..1535
    if (i < 512)       { bqkv[i] = bq[i];        bkvc[i]       = bkc[i];       }
    else if (i < 1024) { bqkv[i] = bk[i - 512];  bkvc[i]       = bvc[i - 512]; }
    else if (i < 1536) { bqkv[i] = bv[i - 1024]; }
}

// LIF over T=4: pre fp32 [4,S] -> spikes fp16 [4,S]
__global__ void lif4h(const float* __restrict__ pre, __half* __restrict__ out, int S)
{
    const int i = blockIdx.x * blockDim.x + threadIdx.x;
    if (i >= S) return;
    float vmem = 0.f;
    #pragma unroll
    for (int t = 0; t < 4; t++) {
        float u = (vmem + pre[(size_t)t * S + i]) * 0.5f;
        if (u >= 1.0f) { out[(size_t)t * S + i] = __float2half(1.0f); vmem = 0.0f; }
        else           { out[(size_t)t * S + i] = __float2half(0.0f); vmem = u;    }
    }
}

// LIF + residual add into x, and write fp16 limbs of the new x
__global__ void lif4_add_split(const float* __restrict__ pre, float* __restrict__ x,
                               __half* __restrict__ a0, __half* __restrict__ a1, int S)
{
    const int i = blockIdx.x * blockDim.x + threadIdx.x;
    if (i >= S) return;
    float vmem = 0.f;
    #pragma unroll
    for (int t = 0; t < 4; t++) {
        const size_t idx = (size_t)t * S + i;
        float u = (vmem + pre[idx]) * 0.5f;
        float xn = x[idx];
        if (u >= 1.0f) { xn += 1.0f; vmem = 0.0f; }
        else           { vmem = u; }
        x[idx] = xn;
        __half h = __float2half(xn);
        a0[idx] = h;
        a1[idx] = __float2half(xn - __half2float(h));
    }
}

// LIF + residual add, final result straight to out
__global__ void lif4_add_out(const float* __restrict__ pre, const float* __restrict__ x,
                             float* __restrict__ out, int S)
{
    const int i = blockIdx.x * blockDim.x + threadIdx.x;
    if (i >= S) return;
    float vmem = 0.f;
    #pragma unroll
    for (int t = 0; t < 4; t++) {
        const size_t idx = (size_t)t * S + i;
        float u = (vmem + pre[idx]) * 0.5f;
        float s;
        if (u >= 1.0f) { s = 1.0f; vmem = 0.0f; }
        else           { s = 0.0f; vmem = u; }
        out[idx] = x[idx] + s;
    }
}

// ---------------- GEMM (exact R10-fallback config): 128x128 tile, 256 thr, 3-stage ------
struct Segs { const __half* a[3]; const __half* w[3]; };

#define DSM 61696    // 3 stages x (A 128x40h + W 128x40h) = 61440 B, + pad

__global__ __launch_bounds__(256) void gemm_u(
    Segs segs, int nseg, const float* __restrict__ bias,
    float* __restrict__ C, int N, int K)
{
    extern __shared__ char dyn[];
    uint32_t base = (smem_u32(dyn) + 15) & ~15u;
    const uint32_t asb = base;
    const uint32_t wsb = base + 30720;

    const int tid  = threadIdx.x;
    const int lane = tid & 31;
    const int warp = tid >> 5;
    const int m0   = blockIdx.y * 128;
    const int n0   = blockIdx.x * 128;

    const int wm = warp >> 2;   // 0..1 -> 64 rows
    const int wn = warp & 3;    // 0..3 -> 32 cols
    const int r  = lane >> 2;
    const int q  = lane & 3;

    const int aRow = (lane & 7) + ((lane >> 3) & 1) * 8;
    const int aCol = (lane >> 4) * 8;
    const int bRow = (lane & 7) + (lane >> 4) * 8;
    const int bCol = ((lane >> 3) & 1) * 8;

    float acc[4][4][4];
    #pragma unroll
    for (int i = 0; i < 4; i++)
        #pragma unroll
        for (int j = 0; j < 4; j++)
            #pragma unroll
            for (int z = 0; z < 4; z++) acc[i][j][z] = 0.f;

    const int ktiles = K >> 5;
    const int TT = nseg * ktiles;

    auto issue = [&](int t) {
        const int buf3 = t % 3;
        const __half* ap = segs.a[t / ktiles];
        const __half* wp = segs.w[t / ktiles];
        const int kk = (t % ktiles) << 5;
        #pragma unroll
        for (int u = 0; u < 2; ++u) {
            const int c   = tid + (u << 8);
            const int row = c >> 2;
            const int col = (c & 3) << 3;  // halves (8 per 16B)
            const __half* sa = ap + (size_t)(m0 + row) * K + kk + col;
            const __half* sw = wp + (size_t)(n0 + row) * K + kk + col;
            const uint32_t da = asb + (uint32_t)(buf3 * 5120 + row * 40 + col) * 2;
            const uint32_t dw = wsb + (uint32_t)(buf3 * 5120 + row * 40 + col) * 2;
            asm volatile("cp.async.cg.shared.global [%0], [%1], 16;" :: "r"(da), "l"(sa));
            asm volatile("cp.async.cg.shared.global [%0], [%1], 16;" :: "r"(dw), "l"(sw));
        }
        asm volatile("cp.async.commit_group;");
    };

    issue(0);
    issue(1);

    for (int tt = 0; tt < TT; ++tt) {
        if (tt == TT - 1) asm volatile("cp.async.wait_group 0;");
        else              asm volatile("cp.async.wait_group 1;");
        __syncthreads();
        if (tt + 2 < TT) issue(tt + 2);

        const int buf3 = tt % 3;
        const uint32_t aT = asb + (uint32_t)(buf3 * 5120) * 2;
        const uint32_t wT = wsb + (uint32_t)(buf3 * 5120) * 2;

        #pragma unroll
        for (int ko = 0; ko < 32; ko += 16) {
            uint32_t af[4][4], bfr[4][2];
            #pragma unroll
            for (int i = 0; i < 4; i++) {
                const uint32_t addr = aT +
                    (uint32_t)((wm * 64 + i * 16 + aRow) * 40 + ko + aCol) * 2;
                asm volatile(
                    "ldmatrix.sync.aligned.m8n8.x4.shared.b16 {%0,%1,%2,%3}, [%4];"
                    : "=r"(af[i][0]), "=r"(af[i][1]), "=r"(af[i][2]), "=r"(af[i][3])
                    : "r"(addr));
            }
            #pragma unroll
            for (int jj = 0; jj < 2; jj++) {
                const uint32_t addr = wT +
                    (uint32_t)((wn * 32 + jj * 16 + bRow) * 40 + ko + bCol) * 2;
                asm volatile(
                    "ldmatrix.sync.aligned.m8n8.x4.shared.b16 {%0,%1,%2,%3}, [%4];"
                    : "=r"(bfr[2*jj][0]), "=r"(bfr[2*jj][1]),
                      "=r"(bfr[2*jj+1][0]), "=r"(bfr[2*jj+1][1])
                    : "r"(addr));
            }
            #pragma unroll
            for (int i = 0; i < 4; i++)
                #pragma unroll
                for (int j = 0; j < 4; j++)
                    asm volatile(
                        "mma.sync.aligned.m16n8k16.row.col.f32.f16.f16.f32 "
                        "{%0,%1,%2,%3}, {%4,%5,%6,%7}, {%8,%9}, {%0,%1,%2,%3};"
                        : "+f"(acc[i][j][0]), "+f"(acc[i][j][1]),
                          "+f"(acc[i][j][2]), "+f"(acc[i][j][3])
                        : "r"(af[i][0]), "r"(af[i][1]), "r"(af[i][2]), "r"(af[i][3]),
                          "r"(bfr[j][0]), "r"(bfr[j][1]));
        }
        __syncthreads();
    }

    // epilogue: bias add + fp32 store
    #pragma unroll
    for (int i = 0; i < 4; i++) {
        const int R0 = m0 + wm * 64 + i * 16 + r;
        #pragma unroll
        for (int j = 0; j < 4; j++) {
            const int C0 = n0 + wn * 32 + j * 8 + 2 * q;
            const float b0 = bias[C0], b1 = bias[C0 + 1];
            float2 o0, o1;
            o0.x = acc[i][j][0] + b0; o0.y = acc[i][j][1] + b1;
            o1.x = acc[i][j][2] + b0; o1.y = acc[i][j][3] + b1;
            *(float2*)&C[(size_t)R0 * N + C0] = o0;
            *(float2*)&C[(size_t)(R0 + 8) * N + C0] = o1;
        }
    }
}

// ---------------- Attention: out = q (kT v) * alpha, binary fp16 spikes, strided ----------
__device__ __forceinline__ void unp8h(const __half* g, float* dst)
{
    uint4 u = *reinterpret_cast<const uint4*>(g);
    const __half2* p = reinterpret_cast<const __half2*>(&u);
    #pragma unroll
    for (int z = 0; z < 4; z++) {
        float2 f = __half22float2(p[z]);
        dst[2 * z] = f.x; dst[2 * z + 1] = f.y;
    }
}

__global__ __launch_bounds__(256) void attn_kernel(
    const __half* __restrict__ q, int qstride,
    const __half* __restrict__ k, const __half* __restrict__ v, int kvstride,
    float* __restrict__ out)
{
    __shared__ float ktv[64][64];
    __shared__ float ks [64][64];
    __shared__ float vs [64][64];

    const int tid     = threadIdx.x;
    const int h       = blockIdx.x & 7;
    const int tb      = blockIdx.x >> 3;
    const int rowbase = tb * 512;
    const int cbase   = h * 64;

    const int d  = tid >> 2;
    const int e0 = (tid & 3) * 16;
    float acc[16];
    #pragma unroll
    for (int j = 0; j < 16; j++) acc[j] = 0.f;

    for (int m0 = 0; m0 < 512; m0 += 64) {
        for (int i = tid; i < 512; i += 256) {
            const int r = i >> 3;
            const int c = (i & 7) * 8;
            const size_t go = (size_t)(rowbase + m0 + r) * kvstride + cbase + c;
            unp8h(k + go, &ks[r][c]);
            unp8h(v + go, &vs[r][c]);
        }
        __syncthreads();
        #pragma unroll 4
        for (int mm = 0; mm < 64; mm++) {
            const float kd = ks[mm][d];
            if (kd != 0.f) {
                #pragma unroll
                for (int j = 0; j < 16; j++) acc[j] += vs[mm][e0 + j];
            }
        }
        __syncthreads();
    }
    #pragma unroll
    for (int j = 0; j < 16; j++) ktv[d][e0 + j] = acc[j];
    __syncthreads();

    for (int n0 = 0; n0 < 512; n0 += 64) {
        for (int i = tid; i < 512; i += 256) {
            const int r = i >> 3;
            const int c = (i & 7) * 8;
            unp8h(q + (size_t)(rowbase + n0 + r) * qstride + cbase + c, &ks[r][c]);
        }
        __syncthreads();
        const int rn  = tid >> 2;
        const int ee0 = (tid & 3) * 16;
        float o[16];
        #pragma unroll
        for (int j = 0; j < 16; j++) o[j] = 0.f;
        #pragma unroll 4
        for (int dd = 0; dd < 64; dd++) {
            const float qd = ks[rn][dd];
            if (qd != 0.f) {
                #pragma unroll
                for (int j = 0; j < 16; j++) o[j] += ktv[dd][ee0 + j];
            }
        }
        #pragma unroll
        for (int j = 0; j < 16; j += 4) {
            float4 ov;
            ov.x = o[j + 0] * 0.125f; ov.y = o[j + 1] * 0.125f;
            ov.z = o[j + 2] * 0.125f; ov.w = o[j + 3] * 0.125f;
            *(float4*)&out[(size_t)(rowbase + n0 + rn) * 512 + cbase + ee0 + j] = ov;
        }
        __syncthreads();
    }
}

// ---------------- host-side orchestration (single stream) ----------------
static void launch_gemm(const __half* a0, const __half* a1, const __half* w,
                        int nseg, const float* bias, float* C, int N, int K)
{
    // nseg==3: fp32-A (h,h)(m,h)(h,m); nseg==2: binary-A (s,h)(s,m)
    Segs s;
    const size_t SW = (size_t)N * K;
    if (nseg == 3) {
        s.a[0] = a0; s.w[0] = w;
        s.a[1] = a1; s.w[1] = w;
        s.a[2] = a0; s.w[2] = w + SW;
    } else {
        s.a[0] = a0; s.w[0] = w;
        s.a[1] = a0; s.w[1] = w + SW;
        s.a[2] = a0; s.w[2] = w;
    }
    cudaFuncSetAttribute(gemm_u, cudaFuncAttributeMaxDynamicSharedMemorySize, DSM);
    gemm_u<<<dim3(N / 128, ROWS / 128), 256, DSM>>>(s, nseg, bias, C, N, K);
}

extern "C" void kernel_launch(void* const* d_in, const int* in_sizes, int n_in,
                              void* d_out, int out_size)
{
    const float* x    = (const float*)d_in[0];
    const float* enc  = (const float*)d_in[1];
    const float* Wq_s = (const float*)d_in[2];  const float* bq_s = (const float*)d_in[3];
    const float* Wk_s = (const float*)d_in[4];  const float* bk_s = (const float*)d_in[5];
    const float* Wv_s = (const float*)d_in[6];  const float* bv_s = (const float*)d_in[7];
    const float* Wo_s = (const float*)d_in[8];  const float* bo_s = (const float*)d_in[9];
    const float* Wq_c = (const float*)d_in[10]; const float* bq_c = (const float*)d_in[11];
    const float* Wk_c = (const float*)d_in[12]; const float* bk_c = (const float*)d_in[13];
    const float* Wv_c = (const float*)d_in[14]; const float* bv_c = (const float*)d_in[15];
    const float* Wo_c = (const float*)d_in[16]; const float* bo_c = (const float*)d_in[17];
    const float* W1   = (const float*)d_in[18]; const float* b1   = (const float*)d_in[19];
    const float* W2   = (const float*)d_in[20]; const float* b2   = (const float*)d_in[21];

    float *gx, *gpre, *gpre2, *bqkv, *bkvc;
    __half *asb, *esb, *qb, *tb, *hb;
    __half *w_qkv, *w_os, *w_qc, *w_kvc, *w_oc, *w_1, *w_2;
    cudaGetSymbolAddress((void**)&gx,    g_x);
    cudaGetSymbolAddress((void**)&gpre,  g_pre);
    cudaGetSymbolAddress((void**)&gpre2, g_pre2);
    cudaGetSymbolAddress((void**)&asb,   g_as);
    cudaGetSymbolAddress((void**)&esb,   g_es);
    cudaGetSymbolAddress((void**)&qb,    g_qb);
    cudaGetSymbolAddress((void**)&tb,    g_tb);
    cudaGetSymbolAddress((void**)&hb,    g_hb);
    cudaGetSymbolAddress((void**)&w_qkv, g_w_qkv);
    cudaGetSymbolAddress((void**)&w_os,  g_w_os);
    cudaGetSymbolAddress((void**)&w_qc,  g_w_qc);
    cudaGetSymbolAddress((void**)&w_kvc, g_w_kvc);
    cudaGetSymbolAddress((void**)&w_oc,  g_w_oc);
    cudaGetSymbolAddress((void**)&w_1,   g_w_1);
    cudaGetSymbolAddress((void**)&w_2,   g_w_2);
    cudaGetSymbolAddress((void**)&bqkv,  g_bqkv);
    cudaGetSymbolAddress((void**)&bkvc,  g_bkvc);

    const size_t SD = (size_t)ROWS * DMODEL;
    __half* as0 = asb; __half* as1 = asb + SD;
    __half* es0 = esb; __half* es1 = esb + SD;

    const int nel = ROWS * DMODEL;
    const int lgD = S512 / 256;
    const dim3 wg512(16, 16);   // wsplit2 grid for 512x512

    // input prep
    copy_split<<<nel / 256, 256>>>(x, gx, as0, as1, nel);
    bias_concat<<<6, 256>>>(bq_s, bk_s, bv_s, bk_c, bv_c, bqkv, bkvc);

    // ---- self-attention block: x = x + ssa(x, x) ----
    wsplit2<<<wg512, 256>>>(Wq_s, w_qkv,            w_qkv + 1536*512,            DMODEL, DMODEL);
    wsplit2<<<wg512, 256>>>(Wk_s, w_qkv + 512*512,  w_qkv + 1536*512 + 512*512,  DMODEL, DMODEL);
    wsplit2<<<wg512, 256>>>(Wv_s, w_qkv + 1024*512, w_qkv + 1536*512 + 1024*512, DMODEL, DMODEL);
    launch_gemm(as0, as1, w_qkv, 3, bqkv, gpre2, 1536, DMODEL);
    lif4h<<<(ROWS/4)*1536 / 256, 256>>>(gpre2, hb, (ROWS/4)*1536);
    attn_kernel<<<128, 256>>>(hb, 1536, hb + 512, hb + 1024, 1536, gpre);
    lif4h<<<lgD, 256>>>(gpre, tb, S512);
    wsplit2<<<wg512, 256>>>(Wo_s, w_os, w_os + 512*512, DMODEL, DMODEL);
    launch_gemm(tb, tb, w_os, 2, bo_s, gpre, DMODEL, DMODEL);
    lif4_add_split<<<lgD, 256>>>(gpre, gx, as0, as1, S512);

    // ---- cross-attention block: x = x + ssa(x, enc) ----
    asplit2<<<nel / 256, 256>>>(enc, es0, es1, nel);
    wsplit2<<<wg512, 256>>>(Wq_c, w_qc, w_qc + 512*512, DMODEL, DMODEL);
    launch_gemm(as0, as1, w_qc, 3, bq_c, gpre, DMODEL, DMODEL);
    wsplit2<<<wg512, 256>>>(Wk_c, w_kvc,           w_kvc + 1024*512,           DMODEL, DMODEL);
    wsplit2<<<wg512, 256>>>(Wv_c, w_kvc + 512*512, w_kvc + 1024*512 + 512*512, DMODEL, DMODEL);
    launch_gemm(es0, es1, w_kvc, 3, bkvc, gpre2, 1024, DMODEL);
    lif4h<<<lgD, 256>>>(gpre, qb, S512);
    lif4h<<<(ROWS/4)*1024 / 256, 256>>>(gpre2, hb, (ROWS/4)*1024);
    attn_kernel<<<128, 256>>>(qb, 512, hb, hb + 512, 1024, gpre);
    lif4h<<<lgD, 256>>>(gpre, tb, S512);
    wsplit2<<<wg512, 256>>>(Wo_c, w_oc, w_oc + 512*512, DMODEL, DMODEL);
    launch_gemm(tb, tb, w_oc, 2, bo_c, gpre, DMODEL, DMODEL);
    lif4_add_split<<<lgD, 256>>>(gpre, gx, as0, as1, S512);

    // ---- MLP block: x = x + lif(lif(x@W1+b1)@W2+b2) ----
    wsplit2<<<dim3(64, 16), 256>>>(W1, w_1, w_1 + (size_t)FDIM*512, DMODEL, FDIM);
    launch_gemm(as0, as1, w_1, 3, b1, gpre2, FDIM, DMODEL);
    lif4h<<<(ROWS/4)*FDIM / 256, 256>>>(gpre2, hb, (ROWS/4)*FDIM);
    wsplit2<<<dim3(16, 64), 256>>>(W2, w_2, w_2 + (size_t)512*FDIM, FDIM, DMODEL);
    launch_gemm(hb, hb, w_2, 2, b2, gpre, DMODEL, FDIM);
    lif4_add_out<<<lgD, 256>>>(gpre, gx, (float*)d_out, S512);
}

// round 13
// speedup vs baseline: 1.1134x; 1.0220x over previous
#include <cuda_runtime.h>
#include <cuda_fp16.h>
#include <stdint.h>

// Problem constants: T=4, B=4, N=512, D=512, F=2048, H=8, dh=64
#define ROWS   8192              // T*B*N
#define DMODEL 512
#define FDIM   2048
#define S512   (ROWS*DMODEL/4)   // B*N*D  (per-timestep spatial size)

// ---------------- scratch (allocation-free: __device__ globals) ----------------
__device__ float g_x   [ROWS*DMODEL];      // running residual stream (fp32)
__device__ float g_pre [ROWS*DMODEL];      // pre-activation scratch (width 512)
__device__ float g_pre2[ROWS*FDIM];        // pre-activation scratch (width 2048)
__device__ __half g_as[2*ROWS*DMODEL];     // activation limbs (x)
__device__ __half g_es[2*ROWS*DMODEL];     // activation limbs (enc)
__device__ __half g_qb[ROWS*DMODEL];       // q spikes
__device__ __half g_kb[ROWS*DMODEL];       // k spikes
__device__ __half g_vb[ROWS*DMODEL];       // v spikes
__device__ __half g_tb[ROWS*DMODEL];       // attn-out spikes
__device__ __half g_hb[ROWS*FDIM];         // MLP hidden spikes
// per-weight limb buffers, transposed [N][K], limb1 at offset N*K
__device__ __half g_w_qs[2*DMODEL*DMODEL];
__device__ __half g_w_ks[2*DMODEL*DMODEL];
__device__ __half g_w_vs[2*DMODEL*DMODEL];
__device__ __half g_w_os[2*DMODEL*DMODEL];
__device__ __half g_w_qc[2*DMODEL*DMODEL];
__device__ __half g_w_kc[2*DMODEL*DMODEL];
__device__ __half g_w_vc[2*DMODEL*DMODEL];
__device__ __half g_w_oc[2*DMODEL*DMODEL];
__device__ __half g_w_1 [2*FDIM*DMODEL];
__device__ __half g_w_2 [2*DMODEL*FDIM];

// ---------------- small helpers ----------------
__device__ __forceinline__ uint32_t smem_u32(const void* p) {
    return (uint32_t)__cvta_generic_to_shared(p);
}

// ---------------- split / fused elementwise kernels ----------------
__global__ void copy_split(const float* __restrict__ X, float* __restrict__ gx,
                           __half* __restrict__ a0, __half* __restrict__ a1, int n)
{
    int i = blockIdx.x * blockDim.x + threadIdx.x;
    if (i >= n) return;
    float v = X[i];
    gx[i] = v;
    __half h = __float2half(v);
    a0[i] = h;
    a1[i] = __float2half(v - __half2float(h));
}

__global__ void asplit2(const float* __restrict__ X,
                        __half* __restrict__ a0, __half* __restrict__ a1, int n)
{
    int i = blockIdx.x * blockDim.x + threadIdx.x;
    if (i >= n) return;
    float v = X[i];
    __half h = __float2half(v);
    a0[i] = h;
    a1[i] = __float2half(v - __half2float(h));
}

// W[K][N] fp32 -> 2 fp16 limbs transposed [N][K] (dst row stride = K)
__global__ void wsplit2(const float* __restrict__ W,
                        __half* __restrict__ w0, __half* __restrict__ w1, int K, int N)
{
    __shared__ float t[32][33];
    const int tid = threadIdx.x;
    const int n0 = blockIdx.x * 32;
    const int k0 = blockIdx.y * 32;
    for (int i = tid; i < 1024; i += 256) {
        int r = i >> 5, c = i & 31;
        t[r][c] = W[(size_t)(k0 + r) * N + n0 + c];
    }
    __syncthreads();
    for (int i = tid; i < 1024; i += 256) {
        int r = i >> 5, c = i & 31;
        float x = t[c][r];
        __half h = __float2half(x);
        __half m = __float2half(x - __half2float(h));
        size_t o = (size_t)(n0 + r) * K + k0 + c;
        w0[o] = h; w1[o] = m;
    }
}

// LIF over T=4: pre fp32 [4,S] -> spikes fp16 [4,S]
__global__ void lif4h(const float* __restrict__ pre, __half* __restrict__ out, int S)
{
    const int i = blockIdx.x * blockDim.x + threadIdx.x;
    if (i >= S) return;
    float vmem = 0.f;
    #pragma unroll
    for (int t = 0; t < 4; t++) {
        float u = (vmem + pre[(size_t)t * S + i]) * 0.5f;
        if (u >= 1.0f) { out[(size_t)t * S + i] = __float2half(1.0f); vmem = 0.0f; }
        else           { out[(size_t)t * S + i] = __float2half(0.0f); vmem = u;    }
    }
}

// LIF + residual add into x, and write fp16 limbs of the new x
__global__ void lif4_add_split(const float* __restrict__ pre, float* __restrict__ x,
                               __half* __restrict__ a0, __half* __restrict__ a1, int S)
{
    const int i = blockIdx.x * blockDim.x + threadIdx.x;
    if (i >= S) return;
    float vmem = 0.f;
    #pragma unroll
    for (int t = 0; t < 4; t++) {
        const size_t idx = (size_t)t * S + i;
        float u = (vmem + pre[idx]) * 0.5f;
        float xn = x[idx];
        if (u >= 1.0f) { xn += 1.0f; vmem = 0.0f; }
        else           { vmem = u; }
        x[idx] = xn;
        __half h = __float2half(xn);
        a0[idx] = h;
        a1[idx] = __float2half(xn - __half2float(h));
    }
}

// LIF + residual add, final result straight to out
__global__ void lif4_add_out(const float* __restrict__ pre, const float* __restrict__ x,
                             float* __restrict__ out, int S)
{
    const int i = blockIdx.x * blockDim.x + threadIdx.x;
    if (i >= S) return;
    float vmem = 0.f;
    #pragma unroll
    for (int t = 0; t < 4; t++) {
        const size_t idx = (size_t)t * S + i;
        float u = (vmem + pre[idx]) * 0.5f;
        float s;
        if (u >= 1.0f) { s = 1.0f; vmem = 0.0f; }
        else           { s = 0.0f; vmem = u; }
        out[idx] = x[idx] + s;
    }
}

// ---------------- GEMM (exact R10 config): 128x128 tile, 256 thr, 3-stage cp.async ------
struct Segs { const __half* a[3]; const __half* w[3]; };

#define DSM 61696    // 3 stages x (A 128x40h + W 128x40h) = 61440 B, + pad

__global__ __launch_bounds__(256) void gemm_u(
    Segs segs, int nseg, const float* __restrict__ bias,
    float* __restrict__ C, int N, int K)
{
    extern __shared__ char dyn[];
    uint32_t base = (smem_u32(dyn) + 15) & ~15u;
    const uint32_t asb = base;
    const uint32_t wsb = base + 30720;

    const int tid  = threadIdx.x;
    const int lane = tid & 31;
    const int warp = tid >> 5;
    const int m0   = blockIdx.y * 128;
    const int n0   = blockIdx.x * 128;

    const int wm = warp >> 2;   // 0..1 -> 64 rows
    const int wn = warp & 3;    // 0..3 -> 32 cols
    const int r  = lane >> 2;
    const int q  = lane & 3;

    const int aRow = (lane & 7) + ((lane >> 3) & 1) * 8;
    const int aCol = (lane >> 4) * 8;
    const int bRow = (lane & 7) + (lane >> 4) * 8;
    const int bCol = ((lane >> 3) & 1) * 8;

    float acc[4][4][4];
    #pragma unroll
    for (int i = 0; i < 4; i++)
        #pragma unroll
        for (int j = 0; j < 4; j++)
            #pragma unroll
            for (int z = 0; z < 4; z++) acc[i][j][z] = 0.f;

    const int ktiles = K >> 5;
    const int TT = nseg * ktiles;

    auto issue = [&](int t) {
        const int buf3 = t % 3;
        const __half* ap = segs.a[t / ktiles];
        const __half* wp = segs.w[t / ktiles];
        const int kk = (t % ktiles) << 5;
        #pragma unroll
        for (int u = 0; u < 2; ++u) {
            const int c   = tid + (u << 8);
            const int row = c >> 2;
            const int col = (c & 3) << 3;  // halves (8 per 16B)
            const __half* sa = ap + (size_t)(m0 + row) * K + kk + col;
            const __half* sw = wp + (size_t)(n0 + row) * K + kk + col;
            const uint32_t da = asb + (uint32_t)(buf3 * 5120 + row * 40 + col) * 2;
            const uint32_t dw = wsb + (uint32_t)(buf3 * 5120 + row * 40 + col) * 2;
            asm volatile("cp.async.cg.shared.global [%0], [%1], 16;" :: "r"(da), "l"(sa));
            asm volatile("cp.async.cg.shared.global [%0], [%1], 16;" :: "r"(dw), "l"(sw));
        }
        asm volatile("cp.async.commit_group;");
    };

    issue(0);
    issue(1);

    for (int tt = 0; tt < TT; ++tt) {
        if (tt == TT - 1) asm volatile("cp.async.wait_group 0;");
        else              asm volatile("cp.async.wait_group 1;");
        __syncthreads();
        if (tt + 2 < TT) issue(tt + 2);

        const int buf3 = tt % 3;
        const uint32_t aT = asb + (uint32_t)(buf3 * 5120) * 2;
        const uint32_t wT = wsb + (uint32_t)(buf3 * 5120) * 2;

        #pragma unroll
        for (int ko = 0; ko < 32; ko += 16) {
            uint32_t af[4][4], bfr[4][2];
            #pragma unroll
            for (int i = 0; i < 4; i++) {
                const uint32_t addr = aT +
                    (uint32_t)((wm * 64 + i * 16 + aRow) * 40 + ko + aCol) * 2;
                asm volatile(
                    "ldmatrix.sync.aligned.m8n8.x4.shared.b16 {%0,%1,%2,%3}, [%4];"
                    : "=r"(af[i][0]), "=r"(af[i][1]), "=r"(af[i][2]), "=r"(af[i][3])
                    : "r"(addr));
            }
            #pragma unroll
            for (int jj = 0; jj < 2; jj++) {
                const uint32_t addr = wT +
                    (uint32_t)((wn * 32 + jj * 16 + bRow) * 40 + ko + bCol) * 2;
                asm volatile(
                    "ldmatrix.sync.aligned.m8n8.x4.shared.b16 {%0,%1,%2,%3}, [%4];"
                    : "=r"(bfr[2*jj][0]), "=r"(bfr[2*jj][1]),
                      "=r"(bfr[2*jj+1][0]), "=r"(bfr[2*jj+1][1])
                    : "r"(addr));
            }
            #pragma unroll
            for (int i = 0; i < 4; i++)
                #pragma unroll
                for (int j = 0; j < 4; j++)
                    asm volatile(
                        "mma.sync.aligned.m16n8k16.row.col.f32.f16.f16.f32 "
                        "{%0,%1,%2,%3}, {%4,%5,%6,%7}, {%8,%9}, {%0,%1,%2,%3};"
                        : "+f"(acc[i][j][0]), "+f"(acc[i][j][1]),
                          "+f"(acc[i][j][2]), "+f"(acc[i][j][3])
                        : "r"(af[i][0]), "r"(af[i][1]), "r"(af[i][2]), "r"(af[i][3]),
                          "r"(bfr[j][0]), "r"(bfr[j][1]));
        }
        __syncthreads();
    }

    // epilogue: bias add + fp32 store
    #pragma unroll
    for (int i = 0; i < 4; i++) {
        const int R0 = m0 + wm * 64 + i * 16 + r;
        #pragma unroll
        for (int j = 0; j < 4; j++) {
            const int C0 = n0 + wn * 32 + j * 8 + 2 * q;
            const float b0 = bias[C0], b1 = bias[C0 + 1];
            float2 o0, o1;
            o0.x = acc[i][j][0] + b0; o0.y = acc[i][j][1] + b1;
            o1.x = acc[i][j][2] + b0; o1.y = acc[i][j][3] + b1;
            *(float2*)&C[(size_t)R0 * N + C0] = o0;
            *(float2*)&C[(size_t)(R0 + 8) * N + C0] = o1;
        }
    }
}

// ---------------- Attention: out = q (kT v) * alpha, binary fp16 spikes (stride 512) ----
__device__ __forceinline__ void unp8h(const __half* g, float* dst)
{
    uint4 u = *reinterpret_cast<const uint4*>(g);
    const __half2* p = reinterpret_cast<const __half2*>(&u);
    #pragma unroll
    for (int z = 0; z < 4; z++) {
        float2 f = __half22float2(p[z]);
        dst[2 * z] = f.x; dst[2 * z + 1] = f.y;
    }
}

__global__ __launch_bounds__(256) void attn_kernel(
    const __half* __restrict__ q, const __half* __restrict__ k,
    const __half* __restrict__ v, float* __restrict__ out)
{
    __shared__ float ktv[64][64];
    __shared__ float ks [64][64];
    __shared__ float vs [64][64];

    const int tid     = threadIdx.x;
    const int h       = blockIdx.x & 7;
    const int tb      = blockIdx.x >> 3;
    const int rowbase = tb * 512;
    const int cbase   = h * 64;

    const int d  = tid >> 2;
    const int e0 = (tid & 3) * 16;
    float acc[16];
    #pragma unroll
    for (int j = 0; j < 16; j++) acc[j] = 0.f;

    for (int m0 = 0; m0 < 512; m0 += 64) {
        for (int i = tid; i < 512; i += 256) {
            const int r = i >> 3;
            const int c = (i & 7) * 8;
            const size_t go = (size_t)(rowbase + m0 + r) * 512 + cbase + c;
            unp8h(k + go, &ks[r][c]);
            unp8h(v + go, &vs[r][c]);
        }
        __syncthreads();
        #pragma unroll 4
        for (int mm = 0; mm < 64; mm++) {
            const float kd = ks[mm][d];
            if (kd != 0.f) {
                #pragma unroll
                for (int j = 0; j < 16; j++) acc[j] += vs[mm][e0 + j];
            }
        }
        __syncthreads();
    }
    #pragma unroll
    for (int j = 0; j < 16; j++) ktv[d][e0 + j] = acc[j];
    __syncthreads();

    for (int n0 = 0; n0 < 512; n0 += 64) {
        for (int i = tid; i < 512; i += 256) {
            const int r = i >> 3;
            const int c = (i & 7) * 8;
            unp8h(q + (size_t)(rowbase + n0 + r) * 512 + cbase + c, &ks[r][c]);
        }
        __syncthreads();
        const int rn  = tid >> 2;
        const int ee0 = (tid & 3) * 16;
        float o[16];
        #pragma unroll
        for (int j = 0; j < 16; j++) o[j] = 0.f;
        #pragma unroll 4
        for (int dd = 0; dd < 64; dd++) {
            const float qd = ks[rn][dd];
            if (qd != 0.f) {
                #pragma unroll
                for (int j = 0; j < 16; j++) o[j] += ktv[dd][ee0 + j];
            }
        }
        #pragma unroll
        for (int j = 0; j < 16; j += 4) {
            float4 ov;
            ov.x = o[j + 0] * 0.125f; ov.y = o[j + 1] * 0.125f;
            ov.z = o[j + 2] * 0.125f; ov.w = o[j + 3] * 0.125f;
            *(float4*)&out[(size_t)(rowbase + n0 + rn) * 512 + cbase + ee0 + j] = ov;
        }
        __syncthreads();
    }
}

// ---------------- host-side orchestration ----------------
static void launch_gemm(const __half* a0, const __half* a1, const __half* w,
                        int nseg, const float* bias, float* C, int N, int K)
{
    // nseg==3: fp32-A (h,h)(m,h)(h,m); nseg==2: binary-A (s,h)(s,m)
    Segs s;
    const size_t SW = (size_t)N * K;
    if (nseg == 3) {
        s.a[0] = a0; s.w[0] = w;
        s.a[1] = a1; s.w[1] = w;
        s.a[2] = a0; s.w[2] = w + SW;
    } else {
        s.a[0] = a0; s.w[0] = w;
        s.a[1] = a0; s.w[1] = w + SW;
        s.a[2] = a0; s.w[2] = w;
    }
    cudaFuncSetAttribute(gemm_u, cudaFuncAttributeMaxDynamicSharedMemorySize, DSM);
    gemm_u<<<dim3(N / 128, ROWS / 128), 256, DSM>>>(s, nseg, bias, C, N, K);
}

extern "C" void kernel_launch(void* const* d_in, const int* in_sizes, int n_in,
                              void* d_out, int out_size)
{
    const float* x    = (const float*)d_in[0];
    const float* enc  = (const float*)d_in[1];
    const float* Wq_s = (const float*)d_in[2];  const float* bq_s = (const float*)d_in[3];
    const float* Wk_s = (const float*)d_in[4];  const float* bk_s = (const float*)d_in[5];
    const float* Wv_s = (const float*)d_in[6];  const float* bv_s = (const float*)d_in[7];
    const float* Wo_s = (const float*)d_in[8];  const float* bo_s = (const float*)d_in[9];
    const float* Wq_c = (const float*)d_in[10]; const float* bq_c = (const float*)d_in[11];
    const float* Wk_c = (const float*)d_in[12]; const float* bk_c = (const float*)d_in[13];
    const float* Wv_c = (const float*)d_in[14]; const float* bv_c = (const float*)d_in[15];
    const float* Wo_c = (const float*)d_in[16]; const float* bo_c = (const float*)d_in[17];
    const float* W1   = (const float*)d_in[18]; const float* b1   = (const float*)d_in[19];
    const float* W2   = (const float*)d_in[20]; const float* b2   = (const float*)d_in[21];

    float *gx, *gpre, *gpre2;
    __half *asb, *esb, *qb, *kb, *vb, *tb, *hb;
    __half *w_qs, *w_ks, *w_vs, *w_os, *w_qc, *w_kc, *w_vc, *w_oc, *w_1, *w_2;
    cudaGetSymbolAddress((void**)&gx,    g_x);
    cudaGetSymbolAddress((void**)&gpre,  g_pre);
    cudaGetSymbolAddress((void**)&gpre2, g_pre2);
    cudaGetSymbolAddress((void**)&asb,   g_as);
    cudaGetSymbolAddress((void**)&esb,   g_es);
    cudaGetSymbolAddress((void**)&qb,    g_qb);
    cudaGetSymbolAddress((void**)&kb,    g_kb);
    cudaGetSymbolAddress((void**)&vb,    g_vb);
    cudaGetSymbolAddress((void**)&tb,    g_tb);
    cudaGetSymbolAddress((void**)&hb,    g_hb);
    cudaGetSymbolAddress((void**)&w_qs,  g_w_qs);
    cudaGetSymbolAddress((void**)&w_ks,  g_w_ks);
    cudaGetSymbolAddress((void**)&w_vs,  g_w_vs);
    cudaGetSymbolAddress((void**)&w_os,  g_w_os);
    cudaGetSymbolAddress((void**)&w_qc,  g_w_qc);
    cudaGetSymbolAddress((void**)&w_kc,  g_w_kc);
    cudaGetSymbolAddress((void**)&w_vc,  g_w_vc);
    cudaGetSymbolAddress((void**)&w_oc,  g_w_oc);
    cudaGetSymbolAddress((void**)&w_1,   g_w_1);
    cudaGetSymbolAddress((void**)&w_2,   g_w_2);

    const size_t SD = (size_t)ROWS * DMODEL;
    __half* as0 = asb; __half* as1 = asb + SD;
    __half* es0 = esb; __half* es1 = esb + SD;

    // lazily-created side stream + events (resources only; captured work is
    // identical on every call)
    static cudaStream_t s2 = nullptr;
    static cudaEvent_t evRoot, ev[6];
    if (!s2) {
        cudaStreamCreateWithFlags(&s2, cudaStreamNonBlocking);
        cudaEventCreateWithFlags(&evRoot, cudaEventDisableTiming);
        for (int i = 0; i < 6; i++) cudaEventCreateWithFlags(&ev[i], cudaEventDisableTiming);
    }

    const int nel = ROWS * DMODEL;
    const int lgD = S512 / 256;
    const dim3 wg512(16, 16);   // wsplit2 grid for 512x512

    // ---- fork side stream: all weight splits + enc split ----
    cudaEventRecord(evRoot, 0);
    cudaStreamWaitEvent(s2, evRoot, 0);

    wsplit2<<<wg512, 256, 0, s2>>>(Wq_s, w_qs, w_qs + 512*512, DMODEL, DMODEL);
    wsplit2<<<wg512, 256, 0, s2>>>(Wk_s, w_ks, w_ks + 512*512, DMODEL, DMODEL);
    wsplit2<<<wg512, 256, 0, s2>>>(Wv_s, w_vs, w_vs + 512*512, DMODEL, DMODEL);
    cudaEventRecord(ev[0], s2);
    wsplit2<<<wg512, 256, 0, s2>>>(Wo_s, w_os, w_os + 512*512, DMODEL, DMODEL);
    cudaEventRecord(ev[1], s2);
    asplit2<<<nel / 256, 256, 0, s2>>>(enc, es0, es1, nel);
    wsplit2<<<wg512, 256, 0, s2>>>(Wq_c, w_qc, w_qc + 512*512, DMODEL, DMODEL);
    wsplit2<<<wg512, 256, 0, s2>>>(Wk_c, w_kc, w_kc + 512*512, DMODEL, DMODEL);
    wsplit2<<<wg512, 256, 0, s2>>>(Wv_c, w_vc, w_vc + 512*512, DMODEL, DMODEL);
    cudaEventRecord(ev[2], s2);
    wsplit2<<<wg512, 256, 0, s2>>>(Wo_c, w_oc, w_oc + 512*512, DMODEL, DMODEL);
    cudaEventRecord(ev[3], s2);
    wsplit2<<<dim3(64, 16), 256, 0, s2>>>(W1, w_1, w_1 + (size_t)FDIM*512, DMODEL, FDIM);
    cudaEventRecord(ev[4], s2);
    wsplit2<<<dim3(16, 64), 256, 0, s2>>>(W2, w_2, w_2 + (size_t)512*FDIM, FDIM, DMODEL);
    cudaEventRecord(ev[5], s2);

    // ---- main stream ----
    copy_split<<<nel / 256, 256>>>(x, gx, as0, as1, nel);

    // self-attention block: x = x + ssa(x, x)
    cudaStreamWaitEvent(0, ev[0], 0);
    launch_gemm(as0, as1, w_qs, 3, bq_s, gpre, DMODEL, DMODEL);
    lif4h<<<lgD, 256>>>(gpre, qb, S512);
    launch_gemm(as0, as1, w_ks, 3, bk_s, gpre, DMODEL, DMODEL);
    lif4h<<<lgD, 256>>>(gpre, kb, S512);
    launch_gemm(as0, as1, w_vs, 3, bv_s, gpre, DMODEL, DMODEL);
    lif4h<<<lgD, 256>>>(gpre, vb, S512);
    attn_kernel<<<128, 256>>>(qb, kb, vb, gpre);
    lif4h<<<lgD, 256>>>(gpre, tb, S512);
    cudaStreamWaitEvent(0, ev[1], 0);
    launch_gemm(tb, tb, w_os, 2, bo_s, gpre, DMODEL, DMODEL);
    lif4_add_split<<<lgD, 256>>>(gpre, gx, as0, as1, S512);

    // cross-attention block: x = x + ssa(x, enc)
    cudaStreamWaitEvent(0, ev[2], 0);
    launch_gemm(as0, as1, w_qc, 3, bq_c, gpre, DMODEL, DMODEL);
    lif4h<<<lgD, 256>>>(gpre, qb, S512);
    launch_gemm(es0, es1, w_kc, 3, bk_c, gpre, DMODEL, DMODEL);
    lif4h<<<lgD, 256>>>(gpre, kb, S512);
    launch_gemm(es0, es1, w_vc, 3, bv_c, gpre, DMODEL, DMODEL);
    lif4h<<<lgD, 256>>>(gpre, vb, S512);
    attn_kernel<<<128, 256>>>(qb, kb, vb, gpre);
    lif4h<<<lgD, 256>>>(gpre, tb, S512);
    cudaStreamWaitEvent(0, ev[3], 0);
    launch_gemm(tb, tb, w_oc, 2, bo_c, gpre, DMODEL, DMODEL);
    lif4_add_split<<<lgD, 256>>>(gpre, gx, as0, as1, S512);

    // MLP block: x = x + lif(lif(x@W1+b1)@W2+b2)
    cudaStreamWaitEvent(0, ev[4], 0);
    launch_gemm(as0, as1, w_1, 3, b1, gpre2, FDIM, DMODEL);
    lif4h<<<(ROWS/4)*FDIM / 256, 256>>>(gpre2, hb, (ROWS/4)*FDIM);
    cudaStreamWaitEvent(0, ev[5], 0);
    launch_gemm(hb, hb, w_2, 2, b2, gpre, DMODEL, FDIM);
    lif4_add_out<<<lgD, 256>>>(gpre, gx, (float*)d_out, S512);
}

// round 14
// speedup vs baseline: 1.1368x; 1.0210x over previous
#include <cuda_runtime.h>
#include <cuda_fp16.h>
#include <stdint.h>

// Problem constants: T=4, B=4, N=512, D=512, F=2048, H=8, dh=64
#define ROWS   8192              // T*B*N
#define DMODEL 512
#define FDIM   2048
#define S512   (ROWS*DMODEL/4)   // B*N*D  (per-timestep spatial size)

// ---------------- scratch (allocation-free: __device__ globals) ----------------
__device__ float g_x   [ROWS*DMODEL];      // running residual stream (fp32)
__device__ float g_pre [ROWS*DMODEL];      // pre-activation scratch (width 512)
__device__ float g_pre2[ROWS*FDIM];        // pre-activation scratch (width 2048 / 3x512)
__device__ __half g_as[2*ROWS*DMODEL];     // activation limbs (x)
__device__ __half g_es[2*ROWS*DMODEL];     // activation limbs (enc)
__device__ __half g_qkvb[3*ROWS*DMODEL];   // q|k|v spikes (contiguous, [3][4][S512])
__device__ __half g_tb[ROWS*DMODEL];       // attn-out spikes
__device__ __half g_hb[ROWS*FDIM];         // MLP hidden spikes
// per-weight limb buffers, transposed [N][K], limb1 at offset N*K
__device__ __half g_w_qs[2*DMODEL*DMODEL];
__device__ __half g_w_ks[2*DMODEL*DMODEL];
__device__ __half g_w_vs[2*DMODEL*DMODEL];
__device__ __half g_w_os[2*DMODEL*DMODEL];
__device__ __half g_w_qc[2*DMODEL*DMODEL];
__device__ __half g_w_kc[2*DMODEL*DMODEL];
__device__ __half g_w_vc[2*DMODEL*DMODEL];
__device__ __half g_w_oc[2*DMODEL*DMODEL];
__device__ __half g_w_1 [2*FDIM*DMODEL];
__device__ __half g_w_2 [2*DMODEL*FDIM];

// ---------------- small helpers ----------------
__device__ __forceinline__ uint32_t smem_u32(const void* p) {
    return (uint32_t)__cvta_generic_to_shared(p);
}

// ---------------- split / fused elementwise kernels ----------------
__global__ void copy_split(const float* __restrict__ X, float* __restrict__ gx,
                           __half* __restrict__ a0, __half* __restrict__ a1, int n)
{
    int i = blockIdx.x * blockDim.x + threadIdx.x;
    if (i >= n) return;
    float v = X[i];
    gx[i] = v;
    __half h = __float2half(v);
    a0[i] = h;
    a1[i] = __float2half(v - __half2float(h));
}

__global__ void asplit2(const float* __restrict__ X,
                        __half* __restrict__ a0, __half* __restrict__ a1, int n)
{
    int i = blockIdx.x * blockDim.x + threadIdx.x;
    if (i >= n) return;
    float v = X[i];
    __half h = __float2half(v);
    a0[i] = h;
    a1[i] = __float2half(v - __half2float(h));
}

// batched weight split: z-th 512x512 weight W[K][N] -> limbs transposed [N][K]
struct WBatch { const float* W[8]; __half* w0[8]; };
__global__ void wsplit_b8(WBatch b)
{
    __shared__ float t[32][33];
    const int z   = blockIdx.z;
    const float* W = b.W[z];
    __half* w0 = b.w0[z];
    __half* w1 = w0 + DMODEL * DMODEL;
    const int tid = threadIdx.x;
    const int n0 = blockIdx.x * 32;
    const int k0 = blockIdx.y * 32;
    for (int i = tid; i < 1024; i += 256) {
        int r = i >> 5, c = i & 31;
        t[r][c] = W[(size_t)(k0 + r) * DMODEL + n0 + c];
    }
    __syncthreads();
    for (int i = tid; i < 1024; i += 256) {
        int r = i >> 5, c = i & 31;
        float x = t[c][r];
        __half h = __float2half(x);
        __half m = __float2half(x - __half2float(h));
        size_t o = (size_t)(n0 + r) * DMODEL + k0 + c;
        w0[o] = h; w1[o] = m;
    }
}

// single weight split (for W1, W2)
__global__ void wsplit2(const float* __restrict__ W,
                        __half* __restrict__ w0, __half* __restrict__ w1, int K, int N)
{
    __shared__ float t[32][33];
    const int tid = threadIdx.x;
    const int n0 = blockIdx.x * 32;
    const int k0 = blockIdx.y * 32;
    for (int i = tid; i < 1024; i += 256) {
        int r = i >> 5, c = i & 31;
        t[r][c] = W[(size_t)(k0 + r) * N + n0 + c];
    }
    __syncthreads();
    for (int i = tid; i < 1024; i += 256) {
        int r = i >> 5, c = i & 31;
        float x = t[c][r];
        __half h = __float2half(x);
        __half m = __float2half(x - __half2float(h));
        size_t o = (size_t)(n0 + r) * K + k0 + c;
        w0[o] = h; w1[o] = m;
    }
}

// LIF over T=4: pre fp32 [4,S] -> spikes fp16 [4,S]
__global__ void lif4h(const float* __restrict__ pre, __half* __restrict__ out, int S)
{
    const int i = blockIdx.x * blockDim.x + threadIdx.x;
    if (i >= S) return;
    float vmem = 0.f;
    #pragma unroll
    for (int t = 0; t < 4; t++) {
        float u = (vmem + pre[(size_t)t * S + i]) * 0.5f;
        if (u >= 1.0f) { out[(size_t)t * S + i] = __float2half(1.0f); vmem = 0.0f; }
        else           { out[(size_t)t * S + i] = __float2half(0.0f); vmem = u;    }
    }
}

// batched LIF over 3 independent [4,S] buffers (contiguous pre and out)
__global__ void lif4h3(const float* __restrict__ pre, __half* __restrict__ out, int S)
{
    const int i = blockIdx.x * blockDim.x + threadIdx.x;
    if (i >= 3 * S) return;
    const int buf = i / S;
    const int j   = i - buf * S;
    const float* p = pre + (size_t)buf * 4 * S;
    __half*      o = out + (size_t)buf * 4 * S;
    float vmem = 0.f;
    #pragma unroll
    for (int t = 0; t < 4; t++) {
        float u = (vmem + p[(size_t)t * S + j]) * 0.5f;
        if (u >= 1.0f) { o[(size_t)t * S + j] = __float2half(1.0f); vmem = 0.0f; }
        else           { o[(size_t)t * S + j] = __float2half(0.0f); vmem = u;    }
    }
}

// LIF + residual add into x, and write fp16 limbs of the new x
__global__ void lif4_add_split(const float* __restrict__ pre, float* __restrict__ x,
                               __half* __restrict__ a0, __half* __restrict__ a1, int S)
{
    const int i = blockIdx.x * blockDim.x + threadIdx.x;
    if (i >= S) return;
    float vmem = 0.f;
    #pragma unroll
    for (int t = 0; t < 4; t++) {
        const size_t idx = (size_t)t * S + i;
        float u = (vmem + pre[idx]) * 0.5f;
        float xn = x[idx];
        if (u >= 1.0f) { xn += 1.0f; vmem = 0.0f; }
        else           { vmem = u; }
        x[idx] = xn;
        __half h = __float2half(xn);
        a0[idx] = h;
        a1[idx] = __float2half(xn - __half2float(h));
    }
}

// LIF + residual add, final result straight to out
__global__ void lif4_add_out(const float* __restrict__ pre, const float* __restrict__ x,
                             float* __restrict__ out, int S)
{
    const int i = blockIdx.x * blockDim.x + threadIdx.x;
    if (i >= S) return;
    float vmem = 0.f;
    #pragma unroll
    for (int t = 0; t < 4; t++) {
        const size_t idx = (size_t)t * S + i;
        float u = (vmem + pre[idx]) * 0.5f;
        float s;
        if (u >= 1.0f) { s = 1.0f; vmem = 0.0f; }
        else           { s = 0.0f; vmem = u; }
        out[idx] = x[idx] + s;
    }
}

// ---------------- GEMM: 128x128 tile, 256 thr, 3-stage cp.async, SINGLE sync/iter ------
struct Segs { const __half* a[3]; const __half* w[3]; };

#define DSM 61696    // 3 stages x (A 128x40h + W 128x40h) = 61440 B, + pad

__global__ __launch_bounds__(256) void gemm_u(
    Segs segs, int nseg, const float* __restrict__ bias,
    float* __restrict__ C, int N, int K)
{
    extern __shared__ char dyn[];
    uint32_t base = (smem_u32(dyn) + 15) & ~15u;
    const uint32_t asb = base;
    const uint32_t wsb = base + 30720;

    const int tid  = threadIdx.x;
    const int lane = tid & 31;
    const int warp = tid >> 5;
    const int m0   = blockIdx.y * 128;
    const int n0   = blockIdx.x * 128;

    const int wm = warp >> 2;   // 0..1 -> 64 rows
    const int wn = warp & 3;    // 0..3 -> 32 cols
    const int r  = lane >> 2;
    const int q  = lane & 3;

    const int aRow = (lane & 7) + ((lane >> 3) & 1) * 8;
    const int aCol = (lane >> 4) * 8;
    const int bRow = (lane & 7) + (lane >> 4) * 8;
    const int bCol = ((lane >> 3) & 1) * 8;

    float acc[4][4][4];
    #pragma unroll
    for (int i = 0; i < 4; i++)
        #pragma unroll
        for (int j = 0; j < 4; j++)
            #pragma unroll
            for (int z = 0; z < 4; z++) acc[i][j][z] = 0.f;

    const int ktiles = K >> 5;
    const int TT = nseg * ktiles;

    auto issue = [&](int t) {
        const int buf3 = t % 3;
        const __half* ap = segs.a[t / ktiles];
        const __half* wp = segs.w[t / ktiles];
        const int kk = (t % ktiles) << 5;
        #pragma unroll
        for (int u = 0; u < 2; ++u) {
            const int c   = tid + (u << 8);
            const int row = c >> 2;
            const int col = (c & 3) << 3;  // halves (8 per 16B)
            const __half* sa = ap + (size_t)(m0 + row) * K + kk + col;
            const __half* sw = wp + (size_t)(n0 + row) * K + kk + col;
            const uint32_t da = asb + (uint32_t)(buf3 * 5120 + row * 40 + col) * 2;
            const uint32_t dw = wsb + (uint32_t)(buf3 * 5120 + row * 40 + col) * 2;
            asm volatile("cp.async.cg.shared.global [%0], [%1], 16;" :: "r"(da), "l"(sa));
            asm volatile("cp.async.cg.shared.global [%0], [%1], 16;" :: "r"(dw), "l"(sw));
        }
        asm volatile("cp.async.commit_group;");
    };

    issue(0);
    issue(1);

    for (int tt = 0; tt < TT; ++tt) {
        if (tt == TT - 1) asm volatile("cp.async.wait_group 0;");
        else              asm volatile("cp.async.wait_group 1;");
        __syncthreads();
        // Single sync per iteration: issue(tt+2) overwrites buf (tt-1)%3, which
        // every warp finished reading before THIS sync; the cp.async data becomes
        // visible to all warps via wait_group + the top sync of iteration tt+2.
        if (tt + 2 < TT) issue(tt + 2);

        const int buf3 = tt % 3;
        const uint32_t aT = asb + (uint32_t)(buf3 * 5120) * 2;
        const uint32_t wT = wsb + (uint32_t)(buf3 * 5120) * 2;

        #pragma unroll
        for (int ko = 0; ko < 32; ko += 16) {
            uint32_t af[4][4], bfr[4][2];
            #pragma unroll
            for (int i = 0; i < 4; i++) {
                const uint32_t addr = aT +
                    (uint32_t)((wm * 64 + i * 16 + aRow) * 40 + ko + aCol) * 2;
                asm volatile(
                    "ldmatrix.sync.aligned.m8n8.x4.shared.b16 {%0,%1,%2,%3}, [%4];"
                    : "=r"(af[i][0]), "=r"(af[i][1]), "=r"(af[i][2]), "=r"(af[i][3])
                    : "r"(addr));
            }
            #pragma unroll
            for (int jj = 0; jj < 2; jj++) {
                const uint32_t addr = wT +
                    (uint32_t)((wn * 32 + jj * 16 + bRow) * 40 + ko + bCol) * 2;
                asm volatile(
                    "ldmatrix.sync.aligned.m8n8.x4.shared.b16 {%0,%1,%2,%3}, [%4];"
                    : "=r"(bfr[2*jj][0]), "=r"(bfr[2*jj][1]),
                      "=r"(bfr[2*jj+1][0]), "=r"(bfr[2*jj+1][1])
                    : "r"(addr));
            }
            #pragma unroll
            for (int i = 0; i < 4; i++)
                #pragma unroll
                for (int j = 0; j < 4; j++)
                    asm volatile(
                        "mma.sync.aligned.m16n8k16.row.col.f32.f16.f16.f32 "
                        "{%0,%1,%2,%3}, {%4,%5,%6,%7}, {%8,%9}, {%0,%1,%2,%3};"
                        : "+f"(acc[i][j][0]), "+f"(acc[i][j][1]),
                          "+f"(acc[i][j][2]), "+f"(acc[i][j][3])
                        : "r"(af[i][0]), "r"(af[i][1]), "r"(af[i][2]), "r"(af[i][3]),
                          "r"(bfr[j][0]), "r"(bfr[j][1]));
        }
    }

    // epilogue: bias add + fp32 store
    #pragma unroll
    for (int i = 0; i < 4; i++) {
        const int R0 = m0 + wm * 64 + i * 16 + r;
        #pragma unroll
        for (int j = 0; j < 4; j++) {
            const int C0 = n0 + wn * 32 + j * 8 + 2 * q;
            const float b0 = bias[C0], b1 = bias[C0 + 1];
            float2 o0, o1;
            o0.x = acc[i][j][0] + b0; o0.y = acc[i][j][1] + b1;
            o1.x = acc[i][j][2] + b0; o1.y = acc[i][j][3] + b1;
            *(float2*)&C[(size_t)R0 * N + C0] = o0;
            *(float2*)&C[(size_t)(R0 + 8) * N + C0] = o1;
        }
    }
}

// ---------------- Attention: out = q (kT v) * alpha, binary fp16 spikes (stride 512) ----
__device__ __forceinline__ void unp8h(const __half* g, float* dst)
{
    uint4 u = *reinterpret_cast<const uint4*>(g);
    const __half2* p = reinterpret_cast<const __half2*>(&u);
    #pragma unroll
    for (int z = 0; z < 4; z++) {
        float2 f = __half22float2(p[z]);
        dst[2 * z] = f.x; dst[2 * z + 1] = f.y;
    }
}

__global__ __launch_bounds__(256) void attn_kernel(
    const __half* __restrict__ q, const __half* __restrict__ k,
    const __half* __restrict__ v, float* __restrict__ out)
{
    __shared__ float ktv[64][64];
    __shared__ float ks [64][64];
    __shared__ float vs [64][64];

    const int tid     = threadIdx.x;
    const int h       = blockIdx.x & 7;
    const int tb      = blockIdx.x >> 3;
    const int rowbase = tb * 512;
    const int cbase   = h * 64;

    const int d  = tid >> 2;
    const int e0 = (tid & 3) * 16;
    float acc[16];
    #pragma unroll
    for (int j = 0; j < 16; j++) acc[j] = 0.f;

    for (int m0 = 0; m0 < 512; m0 += 64) {
        for (int i = tid; i < 512; i += 256) {
            const int r = i >> 3;
            const int c = (i & 7) * 8;
            const size_t go = (size_t)(rowbase + m0 + r) * 512 + cbase + c;
            unp8h(k + go, &ks[r][c]);
            unp8h(v + go, &vs[r][c]);
        }
        __syncthreads();
        #pragma unroll 4
        for (int mm = 0; mm < 64; mm++) {
            const float kd = ks[mm][d];
            if (kd != 0.f) {
                #pragma unroll
                for (int j = 0; j < 16; j++) acc[j] += vs[mm][e0 + j];
            }
        }
        __syncthreads();
    }
    #pragma unroll
    for (int j = 0; j < 16; j++) ktv[d][e0 + j] = acc[j];
    __syncthreads();

    for (int n0 = 0; n0 < 512; n0 += 64) {
        for (int i = tid; i < 512; i += 256) {
            const int r = i >> 3;
            const int c = (i & 7) * 8;
            unp8h(q + (size_t)(rowbase + n0 + r) * 512 + cbase + c, &ks[r][c]);
        }
        __syncthreads();
        const int rn  = tid >> 2;
        const int ee0 = (tid & 3) * 16;
        float o[16];
        #pragma unroll
        for (int j = 0; j < 16; j++) o[j] = 0.f;
        #pragma unroll 4
        for (int dd = 0; dd < 64; dd++) {
            const float qd = ks[rn][dd];
            if (qd != 0.f) {
                #pragma unroll
                for (int j = 0; j < 16; j++) o[j] += ktv[dd][ee0 + j];
            }
        }
        #pragma unroll
        for (int j = 0; j < 16; j += 4) {
            float4 ov;
            ov.x = o[j + 0] * 0.125f; ov.y = o[j + 1] * 0.125f;
            ov.z = o[j + 2] * 0.125f; ov.w = o[j + 3] * 0.125f;
            *(float4*)&out[(size_t)(rowbase + n0 + rn) * 512 + cbase + ee0 + j] = ov;
        }
        __syncthreads();
    }
}

// ---------------- host-side orchestration (single stream) ----------------
static void launch_gemm(const __half* a0, const __half* a1, const __half* w,
                        int nseg, const float* bias, float* C, int N, int K)
{
    // nseg==3: fp32-A (h,h)(m,h)(h,m); nseg==2: binary-A (s,h)(s,m)
    Segs s;
    const size_t SW = (size_t)N * K;
    if (nseg == 3) {
        s.a[0] = a0; s.w[0] = w;
        s.a[1] = a1; s.w[1] = w;
        s.a[2] = a0; s.w[2] = w + SW;
    } else {
        s.a[0] = a0; s.w[0] = w;
        s.a[1] = a0; s.w[1] = w + SW;
        s.a[2] = a0; s.w[2] = w;
    }
    cudaFuncSetAttribute(gemm_u, cudaFuncAttributeMaxDynamicSharedMemorySize, DSM);
    gemm_u<<<dim3(N / 128, ROWS / 128), 256, DSM>>>(s, nseg, bias, C, N, K);
}

extern "C" void kernel_launch(void* const* d_in, const int* in_sizes, int n_in,
                              void* d_out, int out_size)
{
    const float* x    = (const float*)d_in[0];
    const float* enc  = (const float*)d_in[1];
    const float* Wq_s = (const float*)d_in[2];  const float* bq_s = (const float*)d_in[3];
    const float* Wk_s = (const float*)d_in[4];  const float* bk_s = (const float*)d_in[5];
    const float* Wv_s = (const float*)d_in[6];  const float* bv_s = (const float*)d_in[7];
    const float* Wo_s = (const float*)d_in[8];  const float* bo_s = (const float*)d_in[9];
    const float* Wq_c = (const float*)d_in[10]; const float* bq_c = (const float*)d_in[11];
    const float* Wk_c = (const float*)d_in[12]; const float* bk_c = (const float*)d_in[13];
    const float* Wv_c = (const float*)d_in[14]; const float* bv_c = (const float*)d_in[15];
    const float* Wo_c = (const float*)d_in[16]; const float* bo_c = (const float*)d_in[17];
    const float* W1   = (const float*)d_in[18]; const float* b1   = (const float*)d_in[19];
    const float* W2   = (const float*)d_in[20]; const float* b2   = (const float*)d_in[21];

    float *gx, *gpre, *gpre2;
    __half *asb, *esb, *qkvb, *tb, *hb;
    __half *w_qs, *w_ks, *w_vs, *w_os, *w_qc, *w_kc, *w_vc, *w_oc, *w_1, *w_2;
    cudaGetSymbolAddress((void**)&gx,    g_x);
    cudaGetSymbolAddress((void**)&gpre,  g_pre);
    cudaGetSymbolAddress((void**)&gpre2, g_pre2);
    cudaGetSymbolAddress((void**)&asb,   g_as);
    cudaGetSymbolAddress((void**)&esb,   g_es);
    cudaGetSymbolAddress((void**)&qkvb,  g_qkvb);
    cudaGetSymbolAddress((void**)&tb,    g_tb);
    cudaGetSymbolAddress((void**)&hb,    g_hb);
    cudaGetSymbolAddress((void**)&w_qs,  g_w_qs);
    cudaGetSymbolAddress((void**)&w_ks,  g_w_ks);
    cudaGetSymbolAddress((void**)&w_vs,  g_w_vs);
    cudaGetSymbolAddress((void**)&w_os,  g_w_os);
    cudaGetSymbolAddress((void**)&w_qc,  g_w_qc);
    cudaGetSymbolAddress((void**)&w_kc,  g_w_kc);
    cudaGetSymbolAddress((void**)&w_vc,  g_w_vc);
    cudaGetSymbolAddress((void**)&w_oc,  g_w_oc);
    cudaGetSymbolAddress((void**)&w_1,   g_w_1);
    cudaGetSymbolAddress((void**)&w_2,   g_w_2);

    const size_t SD = (size_t)ROWS * DMODEL;   // 4*S512
    __half* as0 = asb; __half* as1 = asb + SD;
    __half* es0 = esb; __half* es1 = esb + SD;
    __half* qb = qkvb;
    __half* kb = qkvb + SD;
    __half* vb = qkvb + 2 * SD;
    float* preQ = gpre2;                        // [4,S512]
    float* preK = gpre2 + SD;
    float* preV = gpre2 + 2 * SD;

    const int nel = ROWS * DMODEL;
    const int lgD = S512 / 256;

    // ---- input + weight preprocessing (single stream, batched) ----
    copy_split<<<nel / 256, 256>>>(x, gx, as0, as1, nel);
    asplit2<<<nel / 256, 256>>>(enc, es0, es1, nel);

    WBatch wb;
    wb.W[0] = Wq_s; wb.w0[0] = w_qs;
    wb.W[1] = Wk_s; wb.w0[1] = w_ks;
    wb.W[2] = Wv_s; wb.w0[2] = w_vs;
    wb.W[3] = Wo_s; wb.w0[3] = w_os;
    wb.W[4] = Wq_c; wb.w0[4] = w_qc;
    wb.W[5] = Wk_c; wb.w0[5] = w_kc;
    wb.W[6] = Wv_c; wb.w0[6] = w_vc;
    wb.W[7] = Wo_c; wb.w0[7] = w_oc;
    wsplit_b8<<<dim3(16, 16, 8), 256>>>(wb);
    wsplit2<<<dim3(64, 16), 256>>>(W1, w_1, w_1 + (size_t)FDIM*512, DMODEL, FDIM);
    wsplit2<<<dim3(16, 64), 256>>>(W2, w_2, w_2 + (size_t)512*FDIM, FDIM, DMODEL);

    // ---- self-attention block: x = x + ssa(x, x) ----
    launch_gemm(as0, as1, w_qs, 3, bq_s, preQ, DMODEL, DMODEL);
    launch_gemm(as0, as1, w_ks, 3, bk_s, preK, DMODEL, DMODEL);
    launch_gemm(as0, as1, w_vs, 3, bv_s, preV, DMODEL, DMODEL);
    lif4h3<<<3 * lgD, 256>>>(gpre2, qkvb, S512);
    attn_kernel<<<128, 256>>>(qb, kb, vb, gpre);
    lif4h<<<lgD, 256>>>(gpre, tb, S512);
    launch_gemm(tb, tb, w_os, 2, bo_s, gpre, DMODEL, DMODEL);
    lif4_add_split<<<lgD, 256>>>(gpre, gx, as0, as1, S512);

    // ---- cross-attention block: x = x + ssa(x, enc) ----
    launch_gemm(as0, as1, w_qc, 3, bq_c, preQ, DMODEL, DMODEL);
    launch_gemm(es0, es1, w_kc, 3, bk_c, preK, DMODEL, DMODEL);
    launch_gemm(es0, es1, w_vc, 3, bv_c, preV, DMODEL, DMODEL);
    lif4h3<<<3 * lgD, 256>>>(gpre2, qkvb, S512);
    attn_kernel<<<128, 256>>>(qb, kb, vb, gpre);
    lif4h<<<lgD, 256>>>(gpre, tb, S512);
    launch_gemm(tb, tb, w_oc, 2, bo_c, gpre, DMODEL, DMODEL);
    lif4_add_split<<<lgD, 256>>>(gpre, gx, as0, as1, S512);

    // ---- MLP block: x = x + lif(lif(x@W1+b1)@W2+b2) ----
    launch_gemm(as0, as1, w_1, 3, b1, gpre2, FDIM, DMODEL);
    lif4h<<<(ROWS/4)*FDIM / 256, 256>>>(gpre2, hb, (ROWS/4)*FDIM);
    launch_gemm(hb, hb, w_2, 2, b2, gpre, DMODEL, FDIM);
    lif4_add_out<<<lgD, 256>>>(gpre, gx, (float*)d_out, S512);
}